// round 14
// baseline (speedup 1.0000x reference)
#include <cuda_runtime.h>
#include <cuda_fp16.h>
#include <math.h>

// Problem constants
#define B_  2
#define T_  2048
#define DM_ 2048
#define H_  16
#define HD_ 128
#define TOT_ 2048
#define MROWS 4096
#define NQKV 6144
#define GK   2048
#define MAIN_ELEMS (MROWS * DM_)

// ---------------- scratch ----------------
__device__ __align__(16) __half g_xh[MROWS * DM_];
__device__ __align__(16) __half g_wq[DM_ * NQKV];
__device__ __align__(16) __half g_wo[TOT_ * DM_];
__device__ __align__(16) __half g_oh[MROWS * TOT_];
__device__ __align__(16) __half g_Q[MROWS * TOT_];
__device__ __align__(16) __half g_K[MROWS * TOT_];
__device__ __align__(16) __half g_V[MROWS * TOT_];

// ---------------- helpers ----------------
__device__ __forceinline__ void ldsm_x4(unsigned& r0, unsigned& r1, unsigned& r2, unsigned& r3,
                                        unsigned addr) {
    asm volatile("ldmatrix.sync.aligned.m8n8.x4.shared.b16 {%0,%1,%2,%3}, [%4];\n"
                 : "=r"(r0), "=r"(r1), "=r"(r2), "=r"(r3) : "r"(addr));
}
__device__ __forceinline__ void ldsm_x4t(unsigned& r0, unsigned& r1, unsigned& r2, unsigned& r3,
                                         unsigned addr) {
    asm volatile("ldmatrix.sync.aligned.m8n8.x4.trans.shared.b16 {%0,%1,%2,%3}, [%4];\n"
                 : "=r"(r0), "=r"(r1), "=r"(r2), "=r"(r3) : "r"(addr));
}
__device__ __forceinline__ void mma16816(float* c, const unsigned* a, const unsigned* b) {
    asm volatile("mma.sync.aligned.m16n8k16.row.col.f32.f16.f16.f32 "
                 "{%0,%1,%2,%3}, {%4,%5,%6,%7}, {%8,%9}, {%0,%1,%2,%3};\n"
                 : "+f"(c[0]), "+f"(c[1]), "+f"(c[2]), "+f"(c[3])
                 : "r"(a[0]), "r"(a[1]), "r"(a[2]), "r"(a[3]), "r"(b[0]), "r"(b[1]));
}
__device__ __forceinline__ unsigned packh2(float x, float y) {
    __half2 h2 = __floats2half2_rn(x, y);
    return *(unsigned*)&h2;
}
__device__ __forceinline__ void cp16(unsigned dst, const void* src) {
    asm volatile("cp.async.ca.shared.global [%0], [%1], 16;\n" :: "r"(dst), "l"(src));
}
__device__ __forceinline__ void cp_commit() {
    asm volatile("cp.async.commit_group;\n" ::: "memory");
}
template <int N>
__device__ __forceinline__ void cp_wait() {
    asm volatile("cp.async.wait_group %0;\n" :: "n"(N) : "memory");
}

// ---------------- fp32 -> fp16 converts ----------------
__global__ __launch_bounds__(256) void conv_f16(const float* __restrict__ src,
                                                __half* __restrict__ dst, int n4) {
    int i = blockIdx.x * blockDim.x + threadIdx.x;
    if (i >= n4) return;
    float4 v = ((const float4*)src)[i];
    uint2 u;
    u.x = packh2(v.x, v.y);
    u.y = packh2(v.z, v.w);
    ((uint2*)dst)[i] = u;
}

__global__ __launch_bounds__(256) void conv_wqkv(const float* __restrict__ Wq,
                                                 const float* __restrict__ Wk,
                                                 const float* __restrict__ Wv,
                                                 __half* __restrict__ dst) {
    int i = blockIdx.x * blockDim.x + threadIdx.x;
    if (i >= DM_ * NQKV / 4) return;
    int k = i / (NQKV / 4);
    int n = (i % (NQKV / 4)) * 4;
    const float* src;
    int nn;
    if (n < 2048)       { src = Wq; nn = n; }
    else if (n < 4096)  { src = Wk; nn = n - 2048; }
    else                { src = Wv; nn = n - 4096; }
    float4 v = *(const float4*)&src[(size_t)k * 2048 + nn];
    uint2 u;
    u.x = packh2(v.x, v.y);
    u.y = packh2(v.z, v.w);
    ((uint2*)dst)[i] = u;
}

// ================= QKV GEMM: 128x384 tile, 64x64 warp tiles, 12 warps =================
#define Q_LDA 72
#define Q_LDB 392            // 384+8
#define Q_STA 0
#define Q_STB 9216           // 128*72 halves
#define Q_STSZ 34304         // halves per stage (68608 B)
#define QKV_SMEM (2 * Q_STSZ * 2)   // 137216 B
#define SRED_LD 392          // fp32 row stride for epilogue (64*392*4 = 100352 B <= QKV_SMEM)

__global__ __launch_bounds__(384, 1) void gemm_qkv(const __half* __restrict__ A,
                                                   const __half* __restrict__ Bm,
                                                   const float* __restrict__ cosp,
                                                   const float* __restrict__ sinp,
                                                   __half* __restrict__ Qd,
                                                   __half* __restrict__ Kd,
                                                   __half* __restrict__ Vd,
                                                   float* __restrict__ outK,
                                                   float* __restrict__ outV,
                                                   int writeKV) {
    extern __shared__ __half sm[];
    const unsigned smu = (unsigned)__cvta_generic_to_shared(sm);
    const int tid = threadIdx.x;
    const int lane = tid & 31, wid = tid >> 5;
    const int wm = wid & 1, wn = wid >> 1;      // warp tile origin (wm*64, wn*64)
    const int m0 = blockIdx.y * 128, n0 = blockIdx.x * 384;

    float acc[4][8][4];
#pragma unroll
    for (int mt = 0; mt < 4; ++mt)
#pragma unroll
        for (int nt = 0; nt < 8; ++nt)
#pragma unroll
            for (int e = 0; e < 4; ++e) acc[mt][nt][e] = 0.f;

    auto prefetch = [&](int s, int k0) {
        unsigned sb2 = smu + (unsigned)(s * Q_STSZ * 2);
        // A: 128 rows x 64 cols = 1024 x 16B
#pragma unroll
        for (int q = 0; q < 3; ++q) {
            int t = tid + q * 384;
            if (t < 1024) {
                int r = t >> 3, c = (t & 7) << 3;
                cp16(sb2 + (Q_STA + r * Q_LDA + c) * 2,
                     A + (size_t)(m0 + r) * GK + k0 + c);
            }
        }
        // B: 64 rows x 384 cols = 3072 x 16B
#pragma unroll
        for (int q = 0; q < 8; ++q) {
            int t = tid + q * 384;
            int r = t / 48, c = (t - r * 48) << 3;
            cp16(sb2 + (Q_STB + r * Q_LDB + c) * 2,
                 Bm + (size_t)(k0 + r) * NQKV + n0 + c);
        }
    };

    prefetch(0, 0);
    cp_commit();
    cp_wait<0>();
    __syncthreads();

    const int lrow = lane & 15;
    const int lcol = (lane >> 4) << 3;
    const int NIT = GK / 64;

    for (int it = 0; it < NIT; ++it) {
        if (it + 1 < NIT) {
            prefetch((it + 1) & 1, (it + 1) * 64);
            cp_commit();
        }
        unsigned sb2 = smu + (unsigned)((it & 1) * Q_STSZ * 2);
        unsigned s_a = sb2 + Q_STA * 2;
        unsigned s_b = sb2 + Q_STB * 2;

#pragma unroll
        for (int ks = 0; ks < 64; ks += 16) {
            unsigned a[4][4];
#pragma unroll
            for (int mt = 0; mt < 4; ++mt) {
                unsigned off = ((wm * 64 + mt * 16 + lrow) * Q_LDA + ks + lcol) * 2;
                ldsm_x4(a[mt][0], a[mt][1], a[mt][2], a[mt][3], s_a + off);
            }
#pragma unroll
            for (int nt2 = 0; nt2 < 4; ++nt2) {
                unsigned off = ((ks + lrow) * Q_LDB + wn * 64 + nt2 * 16 + lcol) * 2;
                unsigned t0, t1, t2, t3;
                ldsm_x4t(t0, t1, t2, t3, s_b + off);
                unsigned b0[2] = {t0, t1}, b1[2] = {t2, t3};
#pragma unroll
                for (int mt = 0; mt < 4; ++mt) {
                    mma16816(acc[mt][2*nt2],   a[mt], b0);
                    mma16816(acc[mt][2*nt2+1], a[mt], b1);
                }
            }
        }
        if (it + 1 < NIT) cp_wait<0>();
        __syncthreads();
    }

    // -------- fused epilogue: 2 passes of 64 rows through smem, rope/convert per 128-chunk --------
    float* sred = (float*)sm;
    const int erow = lane >> 2;
    const int ecol = (lane & 3) << 1;
    const float scale = 0.08838834764831843f;

#pragma unroll
    for (int pass = 0; pass < 2; ++pass) {
        if (wm == pass) {
#pragma unroll
            for (int mt = 0; mt < 4; ++mt)
#pragma unroll
                for (int nt = 0; nt < 8; ++nt) {
                    int r = mt * 16 + erow;
                    int lc = wn * 64 + nt * 8 + ecol;
                    *(float2*)&sred[r * SRED_LD + lc] =
                        make_float2(acc[mt][nt][0], acc[mt][nt][1]);
                    *(float2*)&sred[(r + 8) * SRED_LD + lc] =
                        make_float2(acc[mt][nt][2], acc[mt][nt][3]);
                }
        }
        __syncthreads();
        // 3 chunks x 64 rows x 64 pair-cols = 12288 items over 384 threads
        for (int i = tid; i < 3 * 64 * 64; i += 384) {
            int chunk = i >> 12;
            int rem = i & 4095;
            int r = rem >> 6, d = rem & 63;
            int gc0 = n0 + chunk * 128;
            int sec = gc0 >> 11;
            int h = (gc0 >> 7) & 15;
            int gr = m0 + pass * 64 + r;
            int b = gr >> 11, t = gr & 2047;
            float v1 = sred[r * SRED_LD + chunk * 128 + d];
            float v2 = sred[r * SRED_LD + chunk * 128 + d + 64];
            size_t ob = (((size_t)(b * H_ + h)) * T_ + t) * HD_;
            if (sec == 2) {
                Vd[ob + d]      = __float2half(v1);
                Vd[ob + d + 64] = __float2half(v2);
                if (writeKV) {
                    outV[ob + d]      = v1;
                    outV[ob + d + 64] = v2;
                }
            } else {
                float c1 = cosp[t * HD_ + d],      s1 = sinp[t * HD_ + d];
                float c2 = cosp[t * HD_ + d + 64], s2 = sinp[t * HD_ + d + 64];
                float o1 = v1 * c1 - v2 * s1;
                float o2 = v2 * c2 + v1 * s2;
                if (sec == 0) {
                    Qd[ob + d]      = __float2half(o1 * scale);
                    Qd[ob + d + 64] = __float2half(o2 * scale);
                } else {
                    Kd[ob + d]      = __float2half(o1);
                    Kd[ob + d + 64] = __float2half(o2);
                    if (writeKV) {
                        outK[ob + d]      = o1;
                        outK[ob + d + 64] = o2;
                    }
                }
            }
        }
        __syncthreads();
    }
}

// ================= O-projection GEMM (R12-verified 128x128, BK=64, 2-stage) =================
#define LDA 72
#define LDB 136
#define ST_A 0
#define ST_B 9216
#define ST_SZ 17920
#define GEMM_SMEM (2 * ST_SZ * 2)   // 71680 B

__global__ __launch_bounds__(256, 2) void gemm_f16(const __half* __restrict__ A,
                                                   const __half* __restrict__ Bm,
                                                   float* __restrict__ C, int N) {
    extern __shared__ __half sm[];
    const unsigned smu = (unsigned)__cvta_generic_to_shared(sm);
    const int tid = threadIdx.x;
    const int lane = tid & 31, wid = tid >> 5;
    const int wm = wid & 3, wn = wid >> 2;
    const int m0 = blockIdx.y * 128, n0 = blockIdx.x * 128;

    float acc[2][8][4];
#pragma unroll
    for (int mt = 0; mt < 2; ++mt)
#pragma unroll
        for (int nt = 0; nt < 8; ++nt)
#pragma unroll
            for (int e = 0; e < 4; ++e) acc[mt][nt][e] = 0.f;

    auto prefetch = [&](int s, int k0) {
        unsigned sb2 = smu + (unsigned)(s * ST_SZ * 2);
#pragma unroll
        for (int q = 0; q < 4; ++q) {
            int t = tid + q * 256;
            int arr = t >> 3, acc_ = (t & 7) << 3;
            cp16(sb2 + (ST_A + arr * LDA + acc_) * 2,
                 A + (size_t)(m0 + arr) * GK + k0 + acc_);
            int brr = t >> 4, bcc = (t & 15) << 3;
            cp16(sb2 + (ST_B + brr * LDB + bcc) * 2,
                 Bm + (size_t)(k0 + brr) * N + n0 + bcc);
        }
    };

    prefetch(0, 0);
    cp_commit();
    cp_wait<0>();
    __syncthreads();

    const int lrow = lane & 15;
    const int lcol = (lane >> 4) << 3;
    const int NIT = GK / 64;

    for (int it = 0; it < NIT; ++it) {
        if (it + 1 < NIT) {
            prefetch((it + 1) & 1, (it + 1) * 64);
            cp_commit();
        }
        unsigned sb2 = smu + (unsigned)((it & 1) * ST_SZ * 2);
        unsigned s_a = sb2 + ST_A * 2;
        unsigned s_b = sb2 + ST_B * 2;

#pragma unroll
        for (int ks = 0; ks < 64; ks += 16) {
            unsigned a[2][4];
#pragma unroll
            for (int mt = 0; mt < 2; ++mt) {
                unsigned off = ((wm * 32 + mt * 16 + lrow) * LDA + ks + lcol) * 2;
                ldsm_x4(a[mt][0], a[mt][1], a[mt][2], a[mt][3], s_a + off);
            }
#pragma unroll
            for (int nt2 = 0; nt2 < 4; ++nt2) {
                unsigned off = ((ks + lrow) * LDB + wn * 64 + nt2 * 16 + lcol) * 2;
                unsigned t0, t1, t2, t3;
                ldsm_x4t(t0, t1, t2, t3, s_b + off);
                unsigned b0[2] = {t0, t1}, b1[2] = {t2, t3};
#pragma unroll
                for (int mt = 0; mt < 2; ++mt) {
                    mma16816(acc[mt][2*nt2],   a[mt], b0);
                    mma16816(acc[mt][2*nt2+1], a[mt], b1);
                }
            }
        }
        if (it + 1 < NIT) cp_wait<0>();
        __syncthreads();
    }

    const int erow = lane >> 2;
    const int ecol = (lane & 3) << 1;
#pragma unroll
    for (int mt = 0; mt < 2; ++mt)
#pragma unroll
        for (int nt = 0; nt < 8; ++nt) {
            int gr = m0 + wm * 32 + mt * 16 + erow;
            int gc = n0 + wn * 64 + nt * 8 + ecol;
            *(float2*)&C[(size_t)gr * N + gc]       = make_float2(acc[mt][nt][0], acc[mt][nt][1]);
            *(float2*)&C[(size_t)(gr + 8) * N + gc] = make_float2(acc[mt][nt][2], acc[mt][nt][3]);
        }
}

// ---------------- fp16 flash attention, causal, BM=128, cp.async K/V pipeline ----------------
#define FA_LD 136
#define FA_Q_SZ (128 * FA_LD)
#define FA_T_SZ (64 * FA_LD)
#define FA_SMEM ((FA_Q_SZ + 4 * FA_T_SZ) * 2)   // 104448 B

__global__ __launch_bounds__(256, 2) void flash_attn_tc(
        const __half* __restrict__ Q_, const __half* __restrict__ K_,
        const __half* __restrict__ V_, __half* __restrict__ O) {
    const int qt = gridDim.x - 1 - blockIdx.x;
    const int bh = blockIdx.y;
    const int b = bh >> 4, h = bh & 15;
    const int m0 = qt * 128;
    const size_t base = (size_t)bh * T_ * HD_;

    extern __shared__ __half sb[];
    __half* sQ = sb;
    __half* sK[2] = { sQ + FA_Q_SZ,              sQ + FA_Q_SZ + FA_T_SZ };
    __half* sV[2] = { sQ + FA_Q_SZ + 2*FA_T_SZ,  sQ + FA_Q_SZ + 3*FA_T_SZ };

    const int tid = threadIdx.x;
    const int lane = tid & 31, w = tid >> 5;
    const int g = lane >> 2, t4 = lane & 3;
    const int l8 = lane & 7, sel = lane >> 3;
    const int aro = l8 + ((sel & 1) ? 8 : 0), aco = (sel & 2) ? 8 : 0;
    const int bro = l8 + ((sel & 2) ? 8 : 0), bco = (sel & 1) ? 8 : 0;
    const int vro = l8 + ((sel & 1) ? 8 : 0), vco = (sel & 2) ? 8 : 0;

    for (int i = tid; i < 128 * 16; i += 256) {
        int r = i >> 4, c = (i & 15) * 8;
        *(uint4*)&sQ[r * FA_LD + c] = *(const uint4*)&Q_[base + (size_t)(m0 + r) * HD_ + c];
    }

    unsigned uQ = (unsigned)__cvta_generic_to_shared(sQ);
    unsigned uK[2] = { (unsigned)__cvta_generic_to_shared(sK[0]),
                       (unsigned)__cvta_generic_to_shared(sK[1]) };
    unsigned uV[2] = { (unsigned)__cvta_generic_to_shared(sV[0]),
                       (unsigned)__cvta_generic_to_shared(sV[1]) };

    auto prefetch_kv = [&](int buf, int tt) {
        int n0 = tt * 64;
        unsigned dK = uK[buf], dV = uV[buf];
#pragma unroll
        for (int q = 0; q < 4; ++q) {
            int t = tid + q * 256;
            int r = t >> 4, c = (t & 15) * 8;
            size_t goff = base + (size_t)(n0 + r) * HD_ + c;
            unsigned so = (unsigned)((r * FA_LD + c) * 2);
            cp16(dK + so, K_ + goff);
            cp16(dV + so, V_ + goff);
        }
    };

    float o[16][4];
#pragma unroll
    for (int i = 0; i < 16; ++i)
#pragma unroll
        for (int e = 0; e < 4; ++e) o[i][e] = 0.f;
    float m_i[2] = {-1e30f, -1e30f};
    float l_i[2] = {0.f, 0.f};

    const int ntiles = 2 * qt + 2;

    prefetch_kv(0, 0);
    cp_commit();

    for (int tt = 0; tt < ntiles; ++tt) {
        if (tt + 1 < ntiles) {
            prefetch_kv((tt + 1) & 1, tt + 1);
            cp_commit();
        }
        if (tt + 1 < ntiles) cp_wait<1>();
        else                 cp_wait<0>();
        __syncthreads();

        const int n0 = tt * 64;
        const int bufi = tt & 1;
        unsigned cK = uK[bufi], cV = uV[bufi];

        float s[8][4];
#pragma unroll
        for (int c = 0; c < 8; ++c)
#pragma unroll
            for (int e = 0; e < 4; ++e) s[c][e] = 0.f;

#pragma unroll
        for (int kk = 0; kk < 8; ++kk) {
            unsigned a[4];
            unsigned qoff = (unsigned)(((w * 16 + aro) * FA_LD + kk * 16 + aco) * 2);
            ldsm_x4(a[0], a[1], a[2], a[3], uQ + qoff);
#pragma unroll
            for (int nc = 0; nc < 4; ++nc) {
                unsigned koff = (unsigned)(((nc * 16 + bro) * FA_LD + kk * 16 + bco) * 2);
                unsigned t0, t1, t2, t3;
                ldsm_x4(t0, t1, t2, t3, cK + koff);
                unsigned b0[2] = {t0, t1}, b1[2] = {t2, t3};
                mma16816(s[2*nc],   a, b0);
                mma16816(s[2*nc+1], a, b1);
            }
        }

        if (n0 + 63 > m0 + w * 16) {
            int r0 = m0 + w * 16 + g, r1 = r0 + 8;
#pragma unroll
            for (int c = 0; c < 8; ++c) {
                int col = n0 + c * 8 + 2 * t4;
                if (col     > r0) s[c][0] = -1e30f;
                if (col + 1 > r0) s[c][1] = -1e30f;
                if (col     > r1) s[c][2] = -1e30f;
                if (col + 1 > r1) s[c][3] = -1e30f;
            }
        }

        float mt0 = -1e30f, mt1 = -1e30f;
#pragma unroll
        for (int c = 0; c < 8; ++c) {
            mt0 = fmaxf(mt0, fmaxf(s[c][0], s[c][1]));
            mt1 = fmaxf(mt1, fmaxf(s[c][2], s[c][3]));
        }
        mt0 = fmaxf(mt0, __shfl_xor_sync(0xffffffffu, mt0, 1));
        mt0 = fmaxf(mt0, __shfl_xor_sync(0xffffffffu, mt0, 2));
        mt1 = fmaxf(mt1, __shfl_xor_sync(0xffffffffu, mt1, 1));
        mt1 = fmaxf(mt1, __shfl_xor_sync(0xffffffffu, mt1, 2));

        float mn0 = fmaxf(m_i[0], mt0), mn1 = fmaxf(m_i[1], mt1);
        float al0 = __expf(m_i[0] - mn0), al1 = __expf(m_i[1] - mn1);
        float sum0 = 0.f, sum1 = 0.f;
#pragma unroll
        for (int c = 0; c < 8; ++c) {
            s[c][0] = __expf(s[c][0] - mn0);
            s[c][1] = __expf(s[c][1] - mn0);
            s[c][2] = __expf(s[c][2] - mn1);
            s[c][3] = __expf(s[c][3] - mn1);
            sum0 += s[c][0] + s[c][1];
            sum1 += s[c][2] + s[c][3];
        }
        sum0 += __shfl_xor_sync(0xffffffffu, sum0, 1);
        sum0 += __shfl_xor_sync(0xffffffffu, sum0, 2);
        sum1 += __shfl_xor_sync(0xffffffffu, sum1, 1);
        sum1 += __shfl_xor_sync(0xffffffffu, sum1, 2);

        l_i[0] = l_i[0] * al0 + sum0;
        l_i[1] = l_i[1] * al1 + sum1;
        m_i[0] = mn0; m_i[1] = mn1;

#pragma unroll
        for (int i = 0; i < 16; ++i) {
            o[i][0] *= al0; o[i][1] *= al0;
            o[i][2] *= al1; o[i][3] *= al1;
        }

#pragma unroll
        for (int j = 0; j < 4; ++j) {
            unsigned aP[4];
            aP[0] = packh2(s[2*j][0],   s[2*j][1]);
            aP[1] = packh2(s[2*j][2],   s[2*j][3]);
            aP[2] = packh2(s[2*j+1][0], s[2*j+1][1]);
            aP[3] = packh2(s[2*j+1][2], s[2*j+1][3]);

#pragma unroll
            for (int dd = 0; dd < 8; ++dd) {
                unsigned voff = (unsigned)(((j * 16 + vro) * FA_LD + dd * 16 + vco) * 2);
                unsigned t0, t1, t2, t3;
                ldsm_x4t(t0, t1, t2, t3, cV + voff);
                unsigned b0[2] = {t0, t1}, b1[2] = {t2, t3};
                mma16816(o[2*dd],   aP, b0);
                mma16816(o[2*dd+1], aP, b1);
            }
        }
        __syncthreads();
    }

    float inv0 = 1.f / l_i[0], inv1 = 1.f / l_i[1];
    int trow0 = m0 + w * 16 + g;
#pragma unroll
    for (int c = 0; c < 16; ++c) {
        int gc = h * HD_ + c * 8 + 2 * t4;
        *(__half2*)&O[((size_t)(b * T_ + trow0)) * TOT_ + gc] =
            __floats2half2_rn(o[c][0] * inv0, o[c][1] * inv0);
        *(__half2*)&O[((size_t)(b * T_ + trow0 + 8)) * TOT_ + gc] =
            __floats2half2_rn(o[c][2] * inv1, o[c][3] * inv1);
    }
}

// ---------------- launch ----------------
extern "C" void kernel_launch(void* const* d_in, const int* in_sizes, int n_in,
                              void* d_out, int out_size) {
    const float* x   = (const float*)d_in[0];
    const float* cs  = (const float*)d_in[1];
    const float* sn  = (const float*)d_in[2];
    const float* Wq  = (const float*)d_in[3];
    const float* Wk  = (const float*)d_in[4];
    const float* Wv  = (const float*)d_in[5];
    const float* Wo  = (const float*)d_in[6];
    float* out = (float*)d_out;

    __half *xh, *wq, *wo, *oh, *Qd, *Kd, *Vd;
    cudaGetSymbolAddress((void**)&xh, g_xh);
    cudaGetSymbolAddress((void**)&wq, g_wq);
    cudaGetSymbolAddress((void**)&wo, g_wo);
    cudaGetSymbolAddress((void**)&oh, g_oh);
    cudaGetSymbolAddress((void**)&Qd, g_Q);
    cudaGetSymbolAddress((void**)&Kd, g_K);
    cudaGetSymbolAddress((void**)&Vd, g_V);

    cudaFuncSetAttribute(gemm_qkv, cudaFuncAttributeMaxDynamicSharedMemorySize, QKV_SMEM);
    cudaFuncSetAttribute(gemm_f16, cudaFuncAttributeMaxDynamicSharedMemorySize, GEMM_SMEM);
    cudaFuncSetAttribute(flash_attn_tc, cudaFuncAttributeMaxDynamicSharedMemorySize, FA_SMEM);

    conv_f16<<<(MROWS * DM_ / 4 + 255) / 256, 256>>>(x, xh, MROWS * DM_ / 4);
    conv_wqkv<<<(DM_ * NQKV / 4 + 255) / 256, 256>>>(Wq, Wk, Wv, wq);
    conv_f16<<<(TOT_ * DM_ / 4 + 255) / 256, 256>>>(Wo, wo, TOT_ * DM_ / 4);

    int writeKV = (out_size >= 3 * MAIN_ELEMS) ? 1 : 0;
    float* outK = out + MAIN_ELEMS;
    float* outV = out + 2 * MAIN_ELEMS;

    dim3 qkvGrid(NQKV / 384, MROWS / 128);   // (16, 32)
    gemm_qkv<<<qkvGrid, 384, QKV_SMEM>>>(xh, wq, cs, sn, Qd, Kd, Vd,
                                         writeKV ? outK : (float*)out,
                                         writeKV ? outV : (float*)out, writeKV);

    dim3 faGrid(T_ / 128, B_ * H_);          // (16, 32)
    flash_attn_tc<<<faGrid, 256, FA_SMEM>>>(Qd, Kd, Vd, oh);

    dim3 oGrid(DM_ / 128, MROWS / 128);
    gemm_f16<<<oGrid, 256, GEMM_SMEM>>>(oh, wo, out, DM_);
}

// round 15
// speedup vs baseline: 1.1994x; 1.1994x over previous
#include <cuda_runtime.h>
#include <cuda_fp16.h>
#include <math.h>

// Problem constants
#define B_  2
#define T_  2048
#define DM_ 2048
#define H_  16
#define HD_ 128
#define TOT_ 2048
#define MROWS 4096
#define NQKV 6144
#define GK   2048
#define MAIN_ELEMS (MROWS * DM_)

// ---------------- scratch ----------------
__device__ __align__(16) __half g_xh[MROWS * DM_];
__device__ __align__(16) __half g_wq[DM_ * NQKV];
__device__ __align__(16) __half g_wo[TOT_ * DM_];
__device__ __align__(16) __half g_oh[MROWS * TOT_];   // attention out, fp16 [b,t,h*hd]
__device__ __align__(16) __half g_Q[MROWS * TOT_];    // [b,h,t,hd] fp16
__device__ __align__(16) __half g_K[MROWS * TOT_];
__device__ __align__(16) __half g_V[MROWS * TOT_];

// ---------------- helpers ----------------
__device__ __forceinline__ void ldsm_x4(unsigned& r0, unsigned& r1, unsigned& r2, unsigned& r3,
                                        unsigned addr) {
    asm volatile("ldmatrix.sync.aligned.m8n8.x4.shared.b16 {%0,%1,%2,%3}, [%4];\n"
                 : "=r"(r0), "=r"(r1), "=r"(r2), "=r"(r3) : "r"(addr));
}
__device__ __forceinline__ void ldsm_x4t(unsigned& r0, unsigned& r1, unsigned& r2, unsigned& r3,
                                         unsigned addr) {
    asm volatile("ldmatrix.sync.aligned.m8n8.x4.trans.shared.b16 {%0,%1,%2,%3}, [%4];\n"
                 : "=r"(r0), "=r"(r1), "=r"(r2), "=r"(r3) : "r"(addr));
}
__device__ __forceinline__ void mma16816(float* c, const unsigned* a, const unsigned* b) {
    asm volatile("mma.sync.aligned.m16n8k16.row.col.f32.f16.f16.f32 "
                 "{%0,%1,%2,%3}, {%4,%5,%6,%7}, {%8,%9}, {%0,%1,%2,%3};\n"
                 : "+f"(c[0]), "+f"(c[1]), "+f"(c[2]), "+f"(c[3])
                 : "r"(a[0]), "r"(a[1]), "r"(a[2]), "r"(a[3]), "r"(b[0]), "r"(b[1]));
}
__device__ __forceinline__ unsigned packh2(float x, float y) {
    __half2 h2 = __floats2half2_rn(x, y);
    return *(unsigned*)&h2;
}
__device__ __forceinline__ void cp16(unsigned dst, const void* src) {
    asm volatile("cp.async.ca.shared.global [%0], [%1], 16;\n" :: "r"(dst), "l"(src));
}
__device__ __forceinline__ void cp_commit() {
    asm volatile("cp.async.commit_group;\n" ::: "memory");
}
template <int N>
__device__ __forceinline__ void cp_wait() {
    asm volatile("cp.async.wait_group %0;\n" :: "n"(N) : "memory");
}

// ---------------- merged fp32 -> fp16 converts (x | Wq|Wk|Wv fused | Wo) ----------------
#define N4_X  (MROWS * DM_ / 4)     // 2097152
#define N4_W  (DM_ * NQKV / 4)      // 3145728
#define N4_WO (TOT_ * DM_ / 4)      // 1048576
#define N4_ALL (N4_X + N4_W + N4_WO)

__global__ __launch_bounds__(256) void conv_all(const float* __restrict__ x,
                                                const float* __restrict__ Wq,
                                                const float* __restrict__ Wk,
                                                const float* __restrict__ Wv,
                                                const float* __restrict__ Wo,
                                                __half* __restrict__ xh,
                                                __half* __restrict__ wq,
                                                __half* __restrict__ wo) {
    int i = blockIdx.x * blockDim.x + threadIdx.x;
    if (i >= N4_ALL) return;
    float4 v;
    __half* dst;
    int di;
    if (i < N4_X) {
        v = ((const float4*)x)[i];
        dst = xh; di = i;
    } else if (i < N4_X + N4_W) {
        int j = i - N4_X;
        int k = j / (NQKV / 4);
        int n = (j % (NQKV / 4)) * 4;
        const float* src;
        int nn;
        if (n < 2048)       { src = Wq; nn = n; }
        else if (n < 4096)  { src = Wk; nn = n - 2048; }
        else                { src = Wv; nn = n - 4096; }
        v = *(const float4*)&src[(size_t)k * 2048 + nn];
        dst = wq; di = j;
    } else {
        int j = i - N4_X - N4_W;
        v = ((const float4*)Wo)[j];
        dst = wo; di = j;
    }
    uint2 u;
    u.x = packh2(v.x, v.y);
    u.y = packh2(v.z, v.w);
    ((uint2*)dst)[di] = u;
}

// ---------------- shared GEMM mainloop (R12-verified: BK=64, 2-stage, 2 CTAs/SM) ----------------
#define LDA 72               // 64+8 halves -> 144 B/row
#define LDB 136
#define ST_A 0
#define ST_B 9216            // 128*72 halves
#define ST_SZ 17920          // halves per stage (35840 B)
#define GEMM_SMEM (2 * ST_SZ * 2)   // 71680 B

#define GEMM_MAINLOOP(Aptr, Bptr, Ncols)                                              \
    float acc[2][8][4];                                                               \
    _Pragma("unroll")                                                                 \
    for (int mt = 0; mt < 2; ++mt)                                                    \
        _Pragma("unroll")                                                             \
        for (int nt = 0; nt < 8; ++nt)                                                \
            _Pragma("unroll")                                                         \
            for (int e = 0; e < 4; ++e) acc[mt][nt][e] = 0.f;                         \
    auto prefetch = [&](int s, int k0) {                                              \
        unsigned sb2 = smu + (unsigned)(s * ST_SZ * 2);                               \
        _Pragma("unroll")                                                             \
        for (int q = 0; q < 4; ++q) {                                                 \
            int t = tid + q * 256;                                                    \
            int arr = t >> 3, acc_ = (t & 7) << 3;   /* A: 128 rows x 64 cols */      \
            cp16(sb2 + (ST_A + arr * LDA + acc_) * 2,                                 \
                 (Aptr) + (size_t)(m0 + arr) * GK + k0 + acc_);                       \
            int brr = t >> 4, bcc = (t & 15) << 3;   /* B: 64 rows x 128 cols */      \
            cp16(sb2 + (ST_B + brr * LDB + bcc) * 2,                                  \
                 (Bptr) + (size_t)(k0 + brr) * (Ncols) + n0 + bcc);                   \
        }                                                                             \
    };                                                                                \
    prefetch(0, 0);                                                                   \
    cp_commit();                                                                      \
    cp_wait<0>();                                                                     \
    __syncthreads();                                                                  \
    const int lrow = lane & 15;                                                       \
    const int lcol = (lane >> 4) << 3;                                                \
    const int NIT = GK / 64;                                                          \
    for (int it = 0; it < NIT; ++it) {                                                \
        if (it + 1 < NIT) {                                                           \
            prefetch((it + 1) & 1, (it + 1) * 64);                                    \
            cp_commit();                                                              \
        }                                                                             \
        unsigned sb2 = smu + (unsigned)((it & 1) * ST_SZ * 2);                        \
        unsigned s_a = sb2 + ST_A * 2;                                                \
        unsigned s_b = sb2 + ST_B * 2;                                                \
        _Pragma("unroll")                                                             \
        for (int ks = 0; ks < 64; ks += 16) {                                         \
            unsigned a[2][4];                                                         \
            _Pragma("unroll")                                                         \
            for (int mt = 0; mt < 2; ++mt) {                                          \
                unsigned off = ((wm * 32 + mt * 16 + lrow) * LDA + ks + lcol) * 2;    \
                ldsm_x4(a[mt][0], a[mt][1], a[mt][2], a[mt][3], s_a + off);           \
            }                                                                         \
            _Pragma("unroll")                                                         \
            for (int nt2 = 0; nt2 < 4; ++nt2) {                                       \
                unsigned off = ((ks + lrow) * LDB + wn * 64 + nt2 * 16 + lcol) * 2;   \
                unsigned t0, t1, t2, t3;                                              \
                ldsm_x4t(t0, t1, t2, t3, s_b + off);                                  \
                unsigned b0[2] = {t0, t1}, b1[2] = {t2, t3};                          \
                _Pragma("unroll")                                                     \
                for (int mt = 0; mt < 2; ++mt) {                                      \
                    mma16816(acc[mt][2*nt2],   a[mt], b0);                            \
                    mma16816(acc[mt][2*nt2+1], a[mt], b1);                            \
                }                                                                     \
            }                                                                         \
        }                                                                             \
        if (it + 1 < NIT) cp_wait<0>();                                               \
        __syncthreads();                                                              \
    }

// ---------------- QKV GEMM with fused RoPE/convert epilogue ----------------
#define SRED_LD 132

__global__ __launch_bounds__(256, 2) void gemm_qkv(const __half* __restrict__ A,
                                                   const __half* __restrict__ Bm,
                                                   const float* __restrict__ cosp,
                                                   const float* __restrict__ sinp,
                                                   __half* __restrict__ Qd,
                                                   __half* __restrict__ Kd,
                                                   __half* __restrict__ Vd,
                                                   float* __restrict__ outK,
                                                   float* __restrict__ outV,
                                                   int writeKV) {
    extern __shared__ __half sm[];
    const unsigned smu = (unsigned)__cvta_generic_to_shared(sm);
    const int tid = threadIdx.x;
    const int lane = tid & 31, wid = tid >> 5;
    const int wm = wid & 3, wn = wid >> 2;
    const int m0 = blockIdx.y * 128, n0 = blockIdx.x * 128;

    GEMM_MAINLOOP(A, Bm, NQKV)

    const int sec = n0 >> 11;            // 0=Q, 1=K, 2=V
    const int h   = (n0 >> 7) & 15;
    const int erow = lane >> 2;
    const int ecol = (lane & 3) << 1;
    const float scale = 0.08838834764831843f;

    if (sec == 2) {
#pragma unroll
        for (int mt = 0; mt < 2; ++mt)
#pragma unroll
            for (int nt = 0; nt < 8; ++nt) {
                int lc = wn * 64 + nt * 8 + ecol;
#pragma unroll
                for (int half2row = 0; half2row < 2; ++half2row) {
                    int gr = m0 + wm * 32 + mt * 16 + erow + half2row * 8;
                    int b = gr >> 11, t = gr & 2047;
                    size_t ob = (((size_t)(b * H_ + h)) * T_ + t) * HD_ + lc;
                    float v0 = acc[mt][nt][half2row * 2];
                    float v1 = acc[mt][nt][half2row * 2 + 1];
                    *(__half2*)&Vd[ob] = __floats2half2_rn(v0, v1);
                    if (writeKV) *(float2*)&outV[ob] = make_float2(v0, v1);
                }
            }
    } else {
        float* sred = (float*)sm;
#pragma unroll
        for (int pass = 0; pass < 2; ++pass) {
            if ((wm >> 1) == pass) {
#pragma unroll
                for (int mt = 0; mt < 2; ++mt)
#pragma unroll
                    for (int nt = 0; nt < 8; ++nt) {
                        int r = (wm & 1) * 32 + mt * 16 + erow;
                        int lc = wn * 64 + nt * 8 + ecol;
                        *(float2*)&sred[r * SRED_LD + lc] =
                            make_float2(acc[mt][nt][0], acc[mt][nt][1]);
                        *(float2*)&sred[(r + 8) * SRED_LD + lc] =
                            make_float2(acc[mt][nt][2], acc[mt][nt][3]);
                    }
            }
            __syncthreads();
            for (int i = tid; i < 64 * 64; i += 256) {
                int r = i >> 6, d = i & 63;
                int gr = m0 + pass * 64 + r;
                int b = gr >> 11, t = gr & 2047;
                float v1 = sred[r * SRED_LD + d];
                float v2 = sred[r * SRED_LD + d + 64];
                float c1 = cosp[t * HD_ + d],      s1 = sinp[t * HD_ + d];
                float c2 = cosp[t * HD_ + d + 64], s2 = sinp[t * HD_ + d + 64];
                float o1 = v1 * c1 - v2 * s1;
                float o2 = v2 * c2 + v1 * s2;
                size_t ob = (((size_t)(b * H_ + h)) * T_ + t) * HD_;
                if (sec == 0) {
                    Qd[ob + d]      = __float2half(o1 * scale);
                    Qd[ob + d + 64] = __float2half(o2 * scale);
                } else {
                    Kd[ob + d]      = __float2half(o1);
                    Kd[ob + d + 64] = __float2half(o2);
                    if (writeKV) {
                        outK[ob + d]      = o1;
                        outK[ob + d + 64] = o2;
                    }
                }
            }
            __syncthreads();
        }
    }
}

// ---------------- plain GEMM (O projection): fp32 C ----------------
__global__ __launch_bounds__(256, 2) void gemm_f16(const __half* __restrict__ A,
                                                   const __half* __restrict__ Bm,
                                                   float* __restrict__ C, int N) {
    extern __shared__ __half sm[];
    const unsigned smu = (unsigned)__cvta_generic_to_shared(sm);
    const int tid = threadIdx.x;
    const int lane = tid & 31, wid = tid >> 5;
    const int wm = wid & 3, wn = wid >> 2;
    const int m0 = blockIdx.y * 128, n0 = blockIdx.x * 128;

    GEMM_MAINLOOP(A, Bm, N)

    const int erow = lane >> 2;
    const int ecol = (lane & 3) << 1;
#pragma unroll
    for (int mt = 0; mt < 2; ++mt)
#pragma unroll
        for (int nt = 0; nt < 8; ++nt) {
            int gr = m0 + wm * 32 + mt * 16 + erow;
            int gc = n0 + wn * 64 + nt * 8 + ecol;
            *(float2*)&C[(size_t)gr * N + gc]       = make_float2(acc[mt][nt][0], acc[mt][nt][1]);
            *(float2*)&C[(size_t)(gr + 8) * N + gc] = make_float2(acc[mt][nt][2], acc[mt][nt][3]);
        }
}

// ---------------- fp16 tensor-core flash attention, causal; writes fp16 (R12 version) ----------------
#define FA_LD 136
#define FA_SMEM (3 * 64 * FA_LD * 2)   // 52224 B

__global__ __launch_bounds__(128, 3) void flash_attn_tc(
        const __half* __restrict__ Q_, const __half* __restrict__ K_,
        const __half* __restrict__ V_, __half* __restrict__ O) {
    const int qt = gridDim.x - 1 - blockIdx.x;   // longest work first
    const int bh = blockIdx.y;
    const int b = bh >> 4, h = bh & 15;
    const int m0 = qt * 64;
    const size_t base = (size_t)bh * T_ * HD_;

    extern __shared__ __half sb[];
    __half* sQ = sb;
    __half* sK = sQ + 64 * FA_LD;
    __half* sV = sK + 64 * FA_LD;

    const int tid = threadIdx.x;
    const int lane = tid & 31, w = tid >> 5;
    const int g = lane >> 2, t4 = lane & 3;
    const int l8 = lane & 7, sel = lane >> 3;
    const int aro = l8 + ((sel & 1) ? 8 : 0), aco = (sel & 2) ? 8 : 0;
    const int bro = l8 + ((sel & 2) ? 8 : 0), bco = (sel & 1) ? 8 : 0;
    const int vro = l8 + ((sel & 1) ? 8 : 0), vco = (sel & 2) ? 8 : 0;

    for (int i = tid; i < 64 * 16; i += 128) {
        int r = i >> 4, c = (i & 15) * 8;
        *(uint4*)&sQ[r * FA_LD + c] = *(const uint4*)&Q_[base + (size_t)(m0 + r) * HD_ + c];
    }

    unsigned uQ = (unsigned)__cvta_generic_to_shared(sQ);
    unsigned uK = (unsigned)__cvta_generic_to_shared(sK);
    unsigned uV = (unsigned)__cvta_generic_to_shared(sV);

    float o[16][4];
#pragma unroll
    for (int i = 0; i < 16; ++i)
#pragma unroll
        for (int e = 0; e < 4; ++e) o[i][e] = 0.f;
    float m_i[2] = {-1e30f, -1e30f};
    float l_i[2] = {0.f, 0.f};

    for (int tt = 0; tt <= qt; ++tt) {
        const int n0 = tt * 64;
        __syncthreads();
        for (int i = tid; i < 64 * 16; i += 128) {
            int r = i >> 4, c = (i & 15) * 8;
            size_t goff = base + (size_t)(n0 + r) * HD_ + c;
            *(uint4*)&sK[r * FA_LD + c] = *(const uint4*)&K_[goff];
            *(uint4*)&sV[r * FA_LD + c] = *(const uint4*)&V_[goff];
        }
        __syncthreads();

        float s[8][4];
#pragma unroll
        for (int c = 0; c < 8; ++c)
#pragma unroll
            for (int e = 0; e < 4; ++e) s[c][e] = 0.f;

#pragma unroll
        for (int kk = 0; kk < 8; ++kk) {
            unsigned a[4];
            unsigned qoff = (unsigned)(((w * 16 + aro) * FA_LD + kk * 16 + aco) * 2);
            ldsm_x4(a[0], a[1], a[2], a[3], uQ + qoff);
#pragma unroll
            for (int nc = 0; nc < 4; ++nc) {
                unsigned koff = (unsigned)(((nc * 16 + bro) * FA_LD + kk * 16 + bco) * 2);
                unsigned t0, t1, t2, t3;
                ldsm_x4(t0, t1, t2, t3, uK + koff);
                unsigned b0[2] = {t0, t1}, b1[2] = {t2, t3};
                mma16816(s[2*nc],   a, b0);
                mma16816(s[2*nc+1], a, b1);
            }
        }

        if (tt == qt) {
            int r0 = m0 + w * 16 + g, r1 = r0 + 8;
#pragma unroll
            for (int c = 0; c < 8; ++c) {
                int col = n0 + c * 8 + 2 * t4;
                if (col     > r0) s[c][0] = -1e30f;
                if (col + 1 > r0) s[c][1] = -1e30f;
                if (col     > r1) s[c][2] = -1e30f;
                if (col + 1 > r1) s[c][3] = -1e30f;
            }
        }

        float mt0 = -1e30f, mt1 = -1e30f;
#pragma unroll
        for (int c = 0; c < 8; ++c) {
            mt0 = fmaxf(mt0, fmaxf(s[c][0], s[c][1]));
            mt1 = fmaxf(mt1, fmaxf(s[c][2], s[c][3]));
        }
        mt0 = fmaxf(mt0, __shfl_xor_sync(0xffffffffu, mt0, 1));
        mt0 = fmaxf(mt0, __shfl_xor_sync(0xffffffffu, mt0, 2));
        mt1 = fmaxf(mt1, __shfl_xor_sync(0xffffffffu, mt1, 1));
        mt1 = fmaxf(mt1, __shfl_xor_sync(0xffffffffu, mt1, 2));

        float mn0 = fmaxf(m_i[0], mt0), mn1 = fmaxf(m_i[1], mt1);
        float al0 = __expf(m_i[0] - mn0), al1 = __expf(m_i[1] - mn1);
        float sum0 = 0.f, sum1 = 0.f;
#pragma unroll
        for (int c = 0; c < 8; ++c) {
            s[c][0] = __expf(s[c][0] - mn0);
            s[c][1] = __expf(s[c][1] - mn0);
            s[c][2] = __expf(s[c][2] - mn1);
            s[c][3] = __expf(s[c][3] - mn1);
            sum0 += s[c][0] + s[c][1];
            sum1 += s[c][2] + s[c][3];
        }
        sum0 += __shfl_xor_sync(0xffffffffu, sum0, 1);
        sum0 += __shfl_xor_sync(0xffffffffu, sum0, 2);
        sum1 += __shfl_xor_sync(0xffffffffu, sum1, 1);
        sum1 += __shfl_xor_sync(0xffffffffu, sum1, 2);

        l_i[0] = l_i[0] * al0 + sum0;
        l_i[1] = l_i[1] * al1 + sum1;
        m_i[0] = mn0; m_i[1] = mn1;

#pragma unroll
        for (int i = 0; i < 16; ++i) {
            o[i][0] *= al0; o[i][1] *= al0;
            o[i][2] *= al1; o[i][3] *= al1;
        }

#pragma unroll
        for (int j = 0; j < 4; ++j) {
            unsigned aP[4];
            aP[0] = packh2(s[2*j][0],   s[2*j][1]);
            aP[1] = packh2(s[2*j][2],   s[2*j][3]);
            aP[2] = packh2(s[2*j+1][0], s[2*j+1][1]);
            aP[3] = packh2(s[2*j+1][2], s[2*j+1][3]);

#pragma unroll
            for (int dd = 0; dd < 8; ++dd) {
                unsigned voff = (unsigned)(((j * 16 + vro) * FA_LD + dd * 16 + vco) * 2);
                unsigned t0, t1, t2, t3;
                ldsm_x4t(t0, t1, t2, t3, uV + voff);
                unsigned b0[2] = {t0, t1}, b1[2] = {t2, t3};
                mma16816(o[2*dd],   aP, b0);
                mma16816(o[2*dd+1], aP, b1);
            }
        }
    }

    float inv0 = 1.f / l_i[0], inv1 = 1.f / l_i[1];
    int trow0 = m0 + w * 16 + g;
#pragma unroll
    for (int c = 0; c < 16; ++c) {
        int gc = h * HD_ + c * 8 + 2 * t4;
        *(__half2*)&O[((size_t)(b * T_ + trow0)) * TOT_ + gc] =
            __floats2half2_rn(o[c][0] * inv0, o[c][1] * inv0);
        *(__half2*)&O[((size_t)(b * T_ + trow0 + 8)) * TOT_ + gc] =
            __floats2half2_rn(o[c][2] * inv1, o[c][3] * inv1);
    }
}

// ---------------- launch ----------------
extern "C" void kernel_launch(void* const* d_in, const int* in_sizes, int n_in,
                              void* d_out, int out_size) {
    const float* x   = (const float*)d_in[0];
    const float* cs  = (const float*)d_in[1];
    const float* sn  = (const float*)d_in[2];
    const float* Wq  = (const float*)d_in[3];
    const float* Wk  = (const float*)d_in[4];
    const float* Wv  = (const float*)d_in[5];
    const float* Wo  = (const float*)d_in[6];
    float* out = (float*)d_out;

    __half *xh, *wq, *wo, *oh, *Qd, *Kd, *Vd;
    cudaGetSymbolAddress((void**)&xh, g_xh);
    cudaGetSymbolAddress((void**)&wq, g_wq);
    cudaGetSymbolAddress((void**)&wo, g_wo);
    cudaGetSymbolAddress((void**)&oh, g_oh);
    cudaGetSymbolAddress((void**)&Qd, g_Q);
    cudaGetSymbolAddress((void**)&Kd, g_K);
    cudaGetSymbolAddress((void**)&Vd, g_V);

    cudaFuncSetAttribute(gemm_qkv, cudaFuncAttributeMaxDynamicSharedMemorySize, GEMM_SMEM);
    cudaFuncSetAttribute(gemm_f16, cudaFuncAttributeMaxDynamicSharedMemorySize, GEMM_SMEM);
    cudaFuncSetAttribute(flash_attn_tc, cudaFuncAttributeMaxDynamicSharedMemorySize, FA_SMEM);

    // single merged convert kernel
    conv_all<<<(N4_ALL + 255) / 256, 256>>>(x, Wq, Wk, Wv, Wo, xh, wq, wo);

    int writeKV = (out_size >= 3 * MAIN_ELEMS) ? 1 : 0;
    float* outK = out + MAIN_ELEMS;
    float* outV = out + 2 * MAIN_ELEMS;

    dim3 qkvGrid(NQKV / 128, MROWS / 128);   // (48, 32)
    gemm_qkv<<<qkvGrid, 256, GEMM_SMEM>>>(xh, wq, cs, sn, Qd, Kd, Vd,
                                          writeKV ? outK : (float*)out,
                                          writeKV ? outV : (float*)out, writeKV);

    dim3 faGrid(T_ / 64, B_ * H_);           // (32, 32)
    flash_attn_tc<<<faGrid, 128, FA_SMEM>>>(Qd, Kd, Vd, oh);

    dim3 oGrid(DM_ / 128, MROWS / 128);      // (16, 32)
    gemm_f16<<<oGrid, 256, GEMM_SMEM>>>(oh, wo, out, DM_);
}

// round 16
// speedup vs baseline: 1.2025x; 1.0025x over previous
#include <cuda_runtime.h>
#include <cuda_fp16.h>
#include <math.h>

// Problem constants
#define B_  2
#define T_  2048
#define DM_ 2048
#define H_  16
#define HD_ 128
#define TOT_ 2048
#define MROWS 4096
#define NQKV 6144
#define GK   2048
#define MAIN_ELEMS (MROWS * DM_)

// ---------------- scratch ----------------
__device__ __align__(16) __half g_xh[MROWS * DM_];
__device__ __align__(16) __half g_wq[DM_ * NQKV];
__device__ __align__(16) __half g_wo[TOT_ * DM_];
__device__ __align__(16) __half g_oh[MROWS * TOT_];   // attention out, fp16 [b,t,h*hd]
__device__ __align__(16) __half g_Q[MROWS * TOT_];    // [b,h,t,hd] fp16
__device__ __align__(16) __half g_K[MROWS * TOT_];
__device__ __align__(16) __half g_V[MROWS * TOT_];

// ---------------- helpers ----------------
__device__ __forceinline__ void ldsm_x4(unsigned& r0, unsigned& r1, unsigned& r2, unsigned& r3,
                                        unsigned addr) {
    asm volatile("ldmatrix.sync.aligned.m8n8.x4.shared.b16 {%0,%1,%2,%3}, [%4];\n"
                 : "=r"(r0), "=r"(r1), "=r"(r2), "=r"(r3) : "r"(addr));
}
__device__ __forceinline__ void ldsm_x4t(unsigned& r0, unsigned& r1, unsigned& r2, unsigned& r3,
                                         unsigned addr) {
    asm volatile("ldmatrix.sync.aligned.m8n8.x4.trans.shared.b16 {%0,%1,%2,%3}, [%4];\n"
                 : "=r"(r0), "=r"(r1), "=r"(r2), "=r"(r3) : "r"(addr));
}
__device__ __forceinline__ void mma16816(float* c, const unsigned* a, const unsigned* b) {
    asm volatile("mma.sync.aligned.m16n8k16.row.col.f32.f16.f16.f32 "
                 "{%0,%1,%2,%3}, {%4,%5,%6,%7}, {%8,%9}, {%0,%1,%2,%3};\n"
                 : "+f"(c[0]), "+f"(c[1]), "+f"(c[2]), "+f"(c[3])
                 : "r"(a[0]), "r"(a[1]), "r"(a[2]), "r"(a[3]), "r"(b[0]), "r"(b[1]));
}
__device__ __forceinline__ unsigned packh2(float x, float y) {
    __half2 h2 = __floats2half2_rn(x, y);
    return *(unsigned*)&h2;
}
__device__ __forceinline__ void cp16(unsigned dst, const void* src) {
    asm volatile("cp.async.ca.shared.global [%0], [%1], 16;\n" :: "r"(dst), "l"(src));
}
__device__ __forceinline__ void cp_commit() {
    asm volatile("cp.async.commit_group;\n" ::: "memory");
}
template <int N>
__device__ __forceinline__ void cp_wait() {
    asm volatile("cp.async.wait_group %0;\n" :: "n"(N) : "memory");
}

// ---------------- merged fp32 -> fp16 converts (x | Wq|Wk|Wv fused | Wo) ----------------
#define N4_X  (MROWS * DM_ / 4)
#define N4_W  (DM_ * NQKV / 4)
#define N4_WO (TOT_ * DM_ / 4)
#define N4_ALL (N4_X + N4_W + N4_WO)

__global__ __launch_bounds__(256) void conv_all(const float* __restrict__ x,
                                                const float* __restrict__ Wq,
                                                const float* __restrict__ Wk,
                                                const float* __restrict__ Wv,
                                                const float* __restrict__ Wo,
                                                __half* __restrict__ xh,
                                                __half* __restrict__ wq,
                                                __half* __restrict__ wo) {
    int i = blockIdx.x * blockDim.x + threadIdx.x;
    if (i >= N4_ALL) return;
    float4 v;
    __half* dst;
    int di;
    if (i < N4_X) {
        v = ((const float4*)x)[i];
        dst = xh; di = i;
    } else if (i < N4_X + N4_W) {
        int j = i - N4_X;
        int k = j / (NQKV / 4);
        int n = (j % (NQKV / 4)) * 4;
        const float* src;
        int nn;
        if (n < 2048)       { src = Wq; nn = n; }
        else if (n < 4096)  { src = Wk; nn = n - 2048; }
        else                { src = Wv; nn = n - 4096; }
        v = *(const float4*)&src[(size_t)k * 2048 + nn];
        dst = wq; di = j;
    } else {
        int j = i - N4_X - N4_W;
        v = ((const float4*)Wo)[j];
        dst = wo; di = j;
    }
    uint2 u;
    u.x = packh2(v.x, v.y);
    u.y = packh2(v.z, v.w);
    ((uint2*)dst)[di] = u;
}

// ---------------- shared GEMM mainloop (R12-verified: BK=64, 2-stage, 2 CTAs/SM) ----------------
#define LDA 72
#define LDB 136
#define ST_A 0
#define ST_B 9216
#define ST_SZ 17920
#define GEMM_SMEM (2 * ST_SZ * 2)   // 71680 B

#define GEMM_MAINLOOP(Aptr, Bptr, Ncols)                                              \
    float acc[2][8][4];                                                               \
    _Pragma("unroll")                                                                 \
    for (int mt = 0; mt < 2; ++mt)                                                    \
        _Pragma("unroll")                                                             \
        for (int nt = 0; nt < 8; ++nt)                                                \
            _Pragma("unroll")                                                         \
            for (int e = 0; e < 4; ++e) acc[mt][nt][e] = 0.f;                         \
    auto prefetch = [&](int s, int k0) {                                              \
        unsigned sb2 = smu + (unsigned)(s * ST_SZ * 2);                               \
        _Pragma("unroll")                                                             \
        for (int q = 0; q < 4; ++q) {                                                 \
            int t = tid + q * 256;                                                    \
            int arr = t >> 3, acc_ = (t & 7) << 3;                                    \
            cp16(sb2 + (ST_A + arr * LDA + acc_) * 2,                                 \
                 (Aptr) + (size_t)(m0 + arr) * GK + k0 + acc_);                       \
            int brr = t >> 4, bcc = (t & 15) << 3;                                    \
            cp16(sb2 + (ST_B + brr * LDB + bcc) * 2,                                  \
                 (Bptr) + (size_t)(k0 + brr) * (Ncols) + n0 + bcc);                   \
        }                                                                             \
    };                                                                                \
    prefetch(0, 0);                                                                   \
    cp_commit();                                                                      \
    cp_wait<0>();                                                                     \
    __syncthreads();                                                                  \
    const int lrow = lane & 15;                                                       \
    const int lcol = (lane >> 4) << 3;                                                \
    const int NIT = GK / 64;                                                          \
    for (int it = 0; it < NIT; ++it) {                                                \
        if (it + 1 < NIT) {                                                           \
            prefetch((it + 1) & 1, (it + 1) * 64);                                    \
            cp_commit();                                                              \
        }                                                                             \
        unsigned sb2 = smu + (unsigned)((it & 1) * ST_SZ * 2);                        \
        unsigned s_a = sb2 + ST_A * 2;                                                \
        unsigned s_b = sb2 + ST_B * 2;                                                \
        _Pragma("unroll")                                                             \
        for (int ks = 0; ks < 64; ks += 16) {                                         \
            unsigned a[2][4];                                                         \
            _Pragma("unroll")                                                         \
            for (int mt = 0; mt < 2; ++mt) {                                          \
                unsigned off = ((wm * 32 + mt * 16 + lrow) * LDA + ks + lcol) * 2;    \
                ldsm_x4(a[mt][0], a[mt][1], a[mt][2], a[mt][3], s_a + off);           \
            }                                                                         \
            _Pragma("unroll")                                                         \
            for (int nt2 = 0; nt2 < 4; ++nt2) {                                       \
                unsigned off = ((ks + lrow) * LDB + wn * 64 + nt2 * 16 + lcol) * 2;   \
                unsigned t0, t1, t2, t3;                                              \
                ldsm_x4t(t0, t1, t2, t3, s_b + off);                                  \
                unsigned b0[2] = {t0, t1}, b1[2] = {t2, t3};                          \
                _Pragma("unroll")                                                     \
                for (int mt = 0; mt < 2; ++mt) {                                      \
                    mma16816(acc[mt][2*nt2],   a[mt], b0);                            \
                    mma16816(acc[mt][2*nt2+1], a[mt], b1);                            \
                }                                                                     \
            }                                                                         \
        }                                                                             \
        if (it + 1 < NIT) cp_wait<0>();                                               \
        __syncthreads();                                                              \
    }

// ---------------- QKV GEMM with fused RoPE/convert epilogue ----------------
#define SRED_LD 132

__global__ __launch_bounds__(256, 2) void gemm_qkv(const __half* __restrict__ A,
                                                   const __half* __restrict__ Bm,
                                                   const float* __restrict__ cosp,
                                                   const float* __restrict__ sinp,
                                                   __half* __restrict__ Qd,
                                                   __half* __restrict__ Kd,
                                                   __half* __restrict__ Vd,
                                                   float* __restrict__ outK,
                                                   float* __restrict__ outV,
                                                   int writeKV) {
    extern __shared__ __half sm[];
    const unsigned smu = (unsigned)__cvta_generic_to_shared(sm);
    const int tid = threadIdx.x;
    const int lane = tid & 31, wid = tid >> 5;
    const int wm = wid & 3, wn = wid >> 2;
    const int m0 = blockIdx.y * 128, n0 = blockIdx.x * 128;

    GEMM_MAINLOOP(A, Bm, NQKV)

    const int sec = n0 >> 11;            // 0=Q, 1=K, 2=V
    const int h   = (n0 >> 7) & 15;
    const int erow = lane >> 2;
    const int ecol = (lane & 3) << 1;
    const float scale = 0.08838834764831843f;

    if (sec == 2) {
#pragma unroll
        for (int mt = 0; mt < 2; ++mt)
#pragma unroll
            for (int nt = 0; nt < 8; ++nt) {
                int lc = wn * 64 + nt * 8 + ecol;
#pragma unroll
                for (int half2row = 0; half2row < 2; ++half2row) {
                    int gr = m0 + wm * 32 + mt * 16 + erow + half2row * 8;
                    int b = gr >> 11, t = gr & 2047;
                    size_t ob = (((size_t)(b * H_ + h)) * T_ + t) * HD_ + lc;
                    float v0 = acc[mt][nt][half2row * 2];
                    float v1 = acc[mt][nt][half2row * 2 + 1];
                    *(__half2*)&Vd[ob] = __floats2half2_rn(v0, v1);
                    if (writeKV) *(float2*)&outV[ob] = make_float2(v0, v1);
                }
            }
    } else {
        float* sred = (float*)sm;
#pragma unroll
        for (int pass = 0; pass < 2; ++pass) {
            if ((wm >> 1) == pass) {
#pragma unroll
                for (int mt = 0; mt < 2; ++mt)
#pragma unroll
                    for (int nt = 0; nt < 8; ++nt) {
                        int r = (wm & 1) * 32 + mt * 16 + erow;
                        int lc = wn * 64 + nt * 8 + ecol;
                        *(float2*)&sred[r * SRED_LD + lc] =
                            make_float2(acc[mt][nt][0], acc[mt][nt][1]);
                        *(float2*)&sred[(r + 8) * SRED_LD + lc] =
                            make_float2(acc[mt][nt][2], acc[mt][nt][3]);
                    }
            }
            __syncthreads();
            for (int i = tid; i < 64 * 64; i += 256) {
                int r = i >> 6, d = i & 63;
                int gr = m0 + pass * 64 + r;
                int b = gr >> 11, t = gr & 2047;
                float v1 = sred[r * SRED_LD + d];
                float v2 = sred[r * SRED_LD + d + 64];
                float c1 = cosp[t * HD_ + d],      s1 = sinp[t * HD_ + d];
                float c2 = cosp[t * HD_ + d + 64], s2 = sinp[t * HD_ + d + 64];
                float o1 = v1 * c1 - v2 * s1;
                float o2 = v2 * c2 + v1 * s2;
                size_t ob = (((size_t)(b * H_ + h)) * T_ + t) * HD_;
                if (sec == 0) {
                    Qd[ob + d]      = __float2half(o1 * scale);
                    Qd[ob + d + 64] = __float2half(o2 * scale);
                } else {
                    Kd[ob + d]      = __float2half(o1);
                    Kd[ob + d + 64] = __float2half(o2);
                    if (writeKV) {
                        outK[ob + d]      = o1;
                        outK[ob + d + 64] = o2;
                    }
                }
            }
            __syncthreads();
        }
    }
}

// ---------------- plain GEMM (O projection): fp32 C ----------------
__global__ __launch_bounds__(256, 2) void gemm_f16(const __half* __restrict__ A,
                                                   const __half* __restrict__ Bm,
                                                   float* __restrict__ C, int N) {
    extern __shared__ __half sm[];
    const unsigned smu = (unsigned)__cvta_generic_to_shared(sm);
    const int tid = threadIdx.x;
    const int lane = tid & 31, wid = tid >> 5;
    const int wm = wid & 3, wn = wid >> 2;
    const int m0 = blockIdx.y * 128, n0 = blockIdx.x * 128;

    GEMM_MAINLOOP(A, Bm, N)

    const int erow = lane >> 2;
    const int ecol = (lane & 3) << 1;
#pragma unroll
    for (int mt = 0; mt < 2; ++mt)
#pragma unroll
        for (int nt = 0; nt < 8; ++nt) {
            int gr = m0 + wm * 32 + mt * 16 + erow;
            int gc = n0 + wn * 64 + nt * 8 + ecol;
            *(float2*)&C[(size_t)gr * N + gc]       = make_float2(acc[mt][nt][0], acc[mt][nt][1]);
            *(float2*)&C[(size_t)(gr + 8) * N + gc] = make_float2(acc[mt][nt][2], acc[mt][nt][3]);
        }
}

// ---------------- fp16 tensor-core flash attention, causal; 4 CTAs/SM ----------------
#define FA_LD 136
#define FA_SMEM (3 * 64 * FA_LD * 2)   // 52224 B

__global__ __launch_bounds__(128, 4) void flash_attn_tc(
        const __half* __restrict__ Q_, const __half* __restrict__ K_,
        const __half* __restrict__ V_, __half* __restrict__ O) {
    const int qt = gridDim.x - 1 - blockIdx.x;   // longest work first
    const int bh = blockIdx.y;
    const int b = bh >> 4, h = bh & 15;
    const int m0 = qt * 64;
    const size_t base = (size_t)bh * T_ * HD_;

    extern __shared__ __half sb[];
    __half* sQ = sb;
    __half* sK = sQ + 64 * FA_LD;
    __half* sV = sK + 64 * FA_LD;

    const int tid = threadIdx.x;
    const int lane = tid & 31, w = tid >> 5;
    const int g = lane >> 2, t4 = lane & 3;
    const int l8 = lane & 7, sel = lane >> 3;
    const int aro = l8 + ((sel & 1) ? 8 : 0), aco = (sel & 2) ? 8 : 0;
    const int bro = l8 + ((sel & 2) ? 8 : 0), bco = (sel & 1) ? 8 : 0;
    const int vro = l8 + ((sel & 1) ? 8 : 0), vco = (sel & 2) ? 8 : 0;

    for (int i = tid; i < 64 * 16; i += 128) {
        int r = i >> 4, c = (i & 15) * 8;
        *(uint4*)&sQ[r * FA_LD + c] = *(const uint4*)&Q_[base + (size_t)(m0 + r) * HD_ + c];
    }

    unsigned uQ = (unsigned)__cvta_generic_to_shared(sQ);
    unsigned uK = (unsigned)__cvta_generic_to_shared(sK);
    unsigned uV = (unsigned)__cvta_generic_to_shared(sV);

    float o[16][4];
#pragma unroll
    for (int i = 0; i < 16; ++i)
#pragma unroll
        for (int e = 0; e < 4; ++e) o[i][e] = 0.f;
    float m_i[2] = {-1e30f, -1e30f};
    float l_i[2] = {0.f, 0.f};

    for (int tt = 0; tt <= qt; ++tt) {
        const int n0 = tt * 64;
        __syncthreads();
        for (int i = tid; i < 64 * 16; i += 128) {
            int r = i >> 4, c = (i & 15) * 8;
            size_t goff = base + (size_t)(n0 + r) * HD_ + c;
            *(uint4*)&sK[r * FA_LD + c] = *(const uint4*)&K_[goff];
            *(uint4*)&sV[r * FA_LD + c] = *(const uint4*)&V_[goff];
        }
        __syncthreads();

        float s[8][4];
#pragma unroll
        for (int c = 0; c < 8; ++c)
#pragma unroll
            for (int e = 0; e < 4; ++e) s[c][e] = 0.f;

#pragma unroll
        for (int kk = 0; kk < 8; ++kk) {
            unsigned a[4];
            unsigned qoff = (unsigned)(((w * 16 + aro) * FA_LD + kk * 16 + aco) * 2);
            ldsm_x4(a[0], a[1], a[2], a[3], uQ + qoff);
#pragma unroll
            for (int nc = 0; nc < 4; ++nc) {
                unsigned koff = (unsigned)(((nc * 16 + bro) * FA_LD + kk * 16 + bco) * 2);
                unsigned t0, t1, t2, t3;
                ldsm_x4(t0, t1, t2, t3, uK + koff);
                unsigned b0[2] = {t0, t1}, b1[2] = {t2, t3};
                mma16816(s[2*nc],   a, b0);
                mma16816(s[2*nc+1], a, b1);
            }
        }

        if (tt == qt) {
            int r0 = m0 + w * 16 + g, r1 = r0 + 8;
#pragma unroll
            for (int c = 0; c < 8; ++c) {
                int col = n0 + c * 8 + 2 * t4;
                if (col     > r0) s[c][0] = -1e30f;
                if (col + 1 > r0) s[c][1] = -1e30f;
                if (col     > r1) s[c][2] = -1e30f;
                if (col + 1 > r1) s[c][3] = -1e30f;
            }
        }

        float mt0 = -1e30f, mt1 = -1e30f;
#pragma unroll
        for (int c = 0; c < 8; ++c) {
            mt0 = fmaxf(mt0, fmaxf(s[c][0], s[c][1]));
            mt1 = fmaxf(mt1, fmaxf(s[c][2], s[c][3]));
        }
        mt0 = fmaxf(mt0, __shfl_xor_sync(0xffffffffu, mt0, 1));
        mt0 = fmaxf(mt0, __shfl_xor_sync(0xffffffffu, mt0, 2));
        mt1 = fmaxf(mt1, __shfl_xor_sync(0xffffffffu, mt1, 1));
        mt1 = fmaxf(mt1, __shfl_xor_sync(0xffffffffu, mt1, 2));

        float mn0 = fmaxf(m_i[0], mt0), mn1 = fmaxf(m_i[1], mt1);
        float al0 = __expf(m_i[0] - mn0), al1 = __expf(m_i[1] - mn1);
        float sum0 = 0.f, sum1 = 0.f;
#pragma unroll
        for (int c = 0; c < 8; ++c) {
            s[c][0] = __expf(s[c][0] - mn0);
            s[c][1] = __expf(s[c][1] - mn0);
            s[c][2] = __expf(s[c][2] - mn1);
            s[c][3] = __expf(s[c][3] - mn1);
            sum0 += s[c][0] + s[c][1];
            sum1 += s[c][2] + s[c][3];
        }
        sum0 += __shfl_xor_sync(0xffffffffu, sum0, 1);
        sum0 += __shfl_xor_sync(0xffffffffu, sum0, 2);
        sum1 += __shfl_xor_sync(0xffffffffu, sum1, 1);
        sum1 += __shfl_xor_sync(0xffffffffu, sum1, 2);

        l_i[0] = l_i[0] * al0 + sum0;
        l_i[1] = l_i[1] * al1 + sum1;
        m_i[0] = mn0; m_i[1] = mn1;

#pragma unroll
        for (int i = 0; i < 16; ++i) {
            o[i][0] *= al0; o[i][1] *= al0;
            o[i][2] *= al1; o[i][3] *= al1;
        }

#pragma unroll
        for (int j = 0; j < 4; ++j) {
            unsigned aP[4];
            aP[0] = packh2(s[2*j][0],   s[2*j][1]);
            aP[1] = packh2(s[2*j][2],   s[2*j][3]);
            aP[2] = packh2(s[2*j+1][0], s[2*j+1][1]);
            aP[3] = packh2(s[2*j+1][2], s[2*j+1][3]);

#pragma unroll
            for (int dd = 0; dd < 8; ++dd) {
                unsigned voff = (unsigned)(((j * 16 + vro) * FA_LD + dd * 16 + vco) * 2);
                unsigned t0, t1, t2, t3;
                ldsm_x4t(t0, t1, t2, t3, uV + voff);
                unsigned b0[2] = {t0, t1}, b1[2] = {t2, t3};
                mma16816(o[2*dd],   aP, b0);
                mma16816(o[2*dd+1], aP, b1);
            }
        }
    }

    float inv0 = 1.f / l_i[0], inv1 = 1.f / l_i[1];
    int trow0 = m0 + w * 16 + g;
#pragma unroll
    for (int c = 0; c < 16; ++c) {
        int gc = h * HD_ + c * 8 + 2 * t4;
        *(__half2*)&O[((size_t)(b * T_ + trow0)) * TOT_ + gc] =
            __floats2half2_rn(o[c][0] * inv0, o[c][1] * inv0);
        *(__half2*)&O[((size_t)(b * T_ + trow0 + 8)) * TOT_ + gc] =
            __floats2half2_rn(o[c][2] * inv1, o[c][3] * inv1);
    }
}

// ---------------- launch ----------------
extern "C" void kernel_launch(void* const* d_in, const int* in_sizes, int n_in,
                              void* d_out, int out_size) {
    const float* x   = (const float*)d_in[0];
    const float* cs  = (const float*)d_in[1];
    const float* sn  = (const float*)d_in[2];
    const float* Wq  = (const float*)d_in[3];
    const float* Wk  = (const float*)d_in[4];
    const float* Wv  = (const float*)d_in[5];
    const float* Wo  = (const float*)d_in[6];
    float* out = (float*)d_out;

    __half *xh, *wq, *wo, *oh, *Qd, *Kd, *Vd;
    cudaGetSymbolAddress((void**)&xh, g_xh);
    cudaGetSymbolAddress((void**)&wq, g_wq);
    cudaGetSymbolAddress((void**)&wo, g_wo);
    cudaGetSymbolAddress((void**)&oh, g_oh);
    cudaGetSymbolAddress((void**)&Qd, g_Q);
    cudaGetSymbolAddress((void**)&Kd, g_K);
    cudaGetSymbolAddress((void**)&Vd, g_V);

    cudaFuncSetAttribute(gemm_qkv, cudaFuncAttributeMaxDynamicSharedMemorySize, GEMM_SMEM);
    cudaFuncSetAttribute(gemm_f16, cudaFuncAttributeMaxDynamicSharedMemorySize, GEMM_SMEM);
    cudaFuncSetAttribute(flash_attn_tc, cudaFuncAttributeMaxDynamicSharedMemorySize, FA_SMEM);

    conv_all<<<(N4_ALL + 255) / 256, 256>>>(x, Wq, Wk, Wv, Wo, xh, wq, wo);

    int writeKV = (out_size >= 3 * MAIN_ELEMS) ? 1 : 0;
    float* outK = out + MAIN_ELEMS;
    float* outV = out + 2 * MAIN_ELEMS;

    dim3 qkvGrid(NQKV / 128, MROWS / 128);   // (48, 32)
    gemm_qkv<<<qkvGrid, 256, GEMM_SMEM>>>(xh, wq, cs, sn, Qd, Kd, Vd,
                                          writeKV ? outK : (float*)out,
                                          writeKV ? outV : (float*)out, writeKV);

    dim3 faGrid(T_ / 64, B_ * H_);           // (32, 32)
    flash_attn_tc<<<faGrid, 128, FA_SMEM>>>(Qd, Kd, Vd, oh);

    dim3 oGrid(DM_ / 128, MROWS / 128);      // (16, 32)
    gemm_f16<<<oGrid, 256, GEMM_SMEM>>>(oh, wo, out, DM_);
}